// round 9
// baseline (speedup 1.0000x reference)
#include <cuda_runtime.h>

// NonMaximaSuppression2d: out = x * (x > max over 3x3 neighborhood excluding
// center), replicate padding. (8,4,2048,2048) fp32. HBM-bound stream.
//
// R9 = R8 schedule (8 rows/thread, two phase-separated chunks, interior fast
// path, evict-first stores) but 8-wide strips via Blackwell 256-bit global
// ld/st (ld/st.global.v8.f32 -> LDG.E.256/STG.E.256). Halves LDG/STG/SHFL
// instruction counts at identical bytes to relieve LSU issue pressure
// (STG.128 = 12cyc issue; stores alone were ~50% of LSU capacity).

#define TPB 128          // 128 threads * 8 floats = 1024 px per block in x
#define RPT 8            // output rows per thread (two 4-row chunks)
#define HH  2048
#define WW  2048

__device__ __forceinline__ float max3(float a, float b, float c) {
    return fmaxf(fmaxf(a, b), c);
}

// 256-bit global load: 8 floats. Pure (non-volatile) so ptxas can schedule.
__device__ __forceinline__ void ldg_v8(const float* p, float* r) {
    asm("ld.global.v8.f32 {%0,%1,%2,%3,%4,%5,%6,%7}, [%8];"
        : "=f"(r[0]), "=f"(r[1]), "=f"(r[2]), "=f"(r[3]),
          "=f"(r[4]), "=f"(r[5]), "=f"(r[6]), "=f"(r[7])
        : "l"(p));
}

// 256-bit streaming store: 8 floats, evict-first.
__device__ __forceinline__ void stg_cs_v8(float* p, const float* o) {
    asm volatile("st.global.cs.v8.f32 [%0], {%1,%2,%3,%4,%5,%6,%7,%8};"
                 :: "l"(p),
                    "f"(o[0]), "f"(o[1]), "f"(o[2]), "f"(o[3]),
                    "f"(o[4]), "f"(o[5]), "f"(o[6]), "f"(o[7]));
}

// s[j][0..9]: left halo, 8 strip values, right halo for one padded row.
template <bool CLAMP>
__device__ __forceinline__ void
load_strip(const float* __restrict__ p, int x8, int yy, float s[10]) {
    const int y = CLAMP ? min(max(yy, 0), HH - 1) : yy;
    ldg_v8(p + ((size_t)y << 11) + x8, s + 1);
}

template <bool CLAMP>
__device__ __forceinline__ void
halo_strip(const float* __restrict__ p, int x8, int yy, int lane, float s[10]) {
    float fl = __shfl_up_sync(0xffffffffu, s[8], 1);
    float fr = __shfl_down_sync(0xffffffffu, s[1], 1);
    if (lane == 0 || lane == 31) {
        const int y = CLAMP ? min(max(yy, 0), HH - 1) : yy;
        const float* row = p + ((size_t)y << 11);
        if (lane == 0)  fl = (x8 > 0)      ? __ldg(row + x8 - 1) : s[1];
        if (lane == 31) fr = (x8 + 8 < WW) ? __ldg(row + x8 + 8) : s[8];
    }
    s[0] = fl;
    s[9] = fr;
}

// Compute+store 4 output rows from the 6-row window; qb = &out[ybase][x8].
__device__ __forceinline__ void
compute4(const float s[6][10], float* __restrict__ qb) {
    #pragma unroll
    for (int r = 0; r < 4; r++) {
        const float* st = s[r];
        const float* sm = s[r + 1];
        const float* sb = s[r + 2];
        float o[8];
        #pragma unroll
        for (int i = 0; i < 8; i++) {
            float ft = max3(st[i], st[i + 1], st[i + 2]);
            float fb = max3(sb[i], sb[i + 1], sb[i + 2]);
            float nm = fmaxf(sm[i], sm[i + 2]);          // mid, exclude center
            float nb = fmaxf(fmaxf(ft, fb), nm);
            float c = sm[i + 1];
            o[i] = (c > nb) ? c : 0.0f;
        }
        stg_cs_v8(qb + r * WW, o);
    }
}

template <bool CLAMP>
__device__ __forceinline__ void
nms_tile(const float* __restrict__ p, float* __restrict__ q,
         int x8, int y0, int lane) {
    float s[6][10];

    // ---- Chunk A: batch-load rows y0-1 .. y0+4 (6 independent LDG.256) ----
    #pragma unroll
    for (int j = 0; j < 6; j++)
        load_strip<CLAMP>(p, x8, y0 + j - 1, s[j]);
    #pragma unroll
    for (int j = 0; j < 6; j++)
        halo_strip<CLAMP>(p, x8, y0 + j - 1, lane, s[j]);
    float* qb = q + ((size_t)y0 << 11) + x8;
    compute4(s, qb);

    // ---- Shift window down 4: keep rows y0+3, y0+4 ----
    #pragma unroll
    for (int k = 0; k < 10; k++) { s[0][k] = s[4][k]; s[1][k] = s[5][k]; }

    // ---- Chunk B: batch-load rows y0+5 .. y0+8 (4 independent LDG.256) ----
    #pragma unroll
    for (int j = 2; j < 6; j++)
        load_strip<CLAMP>(p, x8, y0 + j + 3, s[j]);
    #pragma unroll
    for (int j = 2; j < 6; j++)
        halo_strip<CLAMP>(p, x8, y0 + j + 3, lane, s[j]);
    compute4(s, qb + 4 * WW);
}

__global__ void __launch_bounds__(TPB)
nms2d_kernel(const float* __restrict__ x, float* __restrict__ out) {
    const int img = blockIdx.z;
    const size_t base = (size_t)img * HH * WW;
    const float* __restrict__ p = x + base;
    float* __restrict__ q = out + base;

    const int lane = threadIdx.x & 31;
    const int x8 = (blockIdx.x * TPB + threadIdx.x) * 8;
    const int y0 = blockIdx.y * RPT;

    if (y0 > 0 && y0 + RPT < HH) {
        nms_tile<false>(p, q, x8, y0, lane);   // interior: no y clamps
    } else {
        nms_tile<true>(p, q, x8, y0, lane);    // top/bottom edge strips
    }
}

extern "C" void kernel_launch(void* const* d_in, const int* in_sizes, int n_in,
                              void* d_out, int out_size) {
    const float* x = (const float*)d_in[0];
    float* out = (float*)d_out;

    const int n_img = in_sizes[0] / (HH * WW);   // 32

    dim3 block(TPB, 1, 1);
    dim3 grid(WW / (TPB * 8), HH / RPT, n_img);
    nms2d_kernel<<<grid, block>>>(x, out);
}